// round 6
// baseline (speedup 1.0000x reference)
#include <cuda_runtime.h>
#include <math.h>

#define BATCH   128
#define IN_DIM  784
#define HIDDEN  100
#define MODES   10
#define NSTATES 2002
#define NCLS    10
#define SCHUNKS 8

// ---------------- scratch (__device__ globals; no allocation allowed) ------
__device__ float g_h[BATCH * HIDDEN];               // sigmoid activations
__device__ float g_part[BATCH * SCHUNKS * NCLS];    // partial W2 sums

// binomial C(n,k), n=0..13, k=0..4
__device__ const short g_binom[14][5] = {
    {1, 0, 0, 0, 0},  {1, 1, 0, 0, 0},   {1, 2, 1, 0, 0},    {1, 3, 3, 1, 0},
    {1, 4, 6, 4, 1},  {1, 5,10,10, 5},   {1, 6,15,20,15},    {1, 7,21,35,35},
    {1, 8,28,56,70},  {1, 9,36,84,126},  {1,10,45,120,210},  {1,11,55,165,330},
    {1,12,66,220,495},{1,13,78,286,715}
};

typedef unsigned long long ull;

__device__ __forceinline__ ull pk2(float x, float y) {
    ull r; asm("mov.b64 %0, {%1,%2};" : "=l"(r) : "f"(x), "f"(y)); return r;
}
__device__ __forceinline__ float2 upk2(ull v) {
    float2 r; asm("mov.b64 {%0,%1}, %2;" : "=f"(r.x), "=f"(r.y) : "l"(v)); return r;
}
__device__ __forceinline__ ull padd(ull a, ull b) {
    ull r; asm("add.rn.f32x2 %0, %1, %2;" : "=l"(r) : "l"(a), "l"(b)); return r;
}
__device__ __forceinline__ ull pfma(ull a, ull b, ull c) {
    ull r; asm("fma.rn.f32x2 %0, %1, %2, %3;" : "=l"(r) : "l"(a), "l"(b), "l"(c)); return r;
}

__device__ __forceinline__ float2 cmul(float2 a, float2 b) {
    return make_float2(fmaf(a.x, b.x, -(a.y * b.y)),
                       fmaf(a.x, b.y,  a.y * b.x));
}

// ---------------- kernel 1: MLP, 4b x 4h warp tiles, K split x2 -----------
// 200 blocks x 256 thr = 1600 warps. Warp pair (even/odd) shares a (b,h)
// tile, each takes half of K. 16-value binary-fold warp reduction.
__global__ void __launch_bounds__(256) k_mlp(const float* __restrict__ x,
                                             const float* __restrict__ W1,
                                             const float* __restrict__ b1) {
    int wid  = threadIdx.x >> 5;
    int lane = threadIdx.x & 31;
    int pid  = wid >> 1;                 // tile-pair in block (0..3)
    int kh   = wid & 1;                  // K half
    int g    = blockIdx.x * 4 + pid;     // 800 tile pairs
    int b0   = (g & 31) * 4;
    int h0   = (g >> 5) * 4;

    __shared__ float part[4][16];

    const float4* xr0 = (const float4*)(x  + (b0 + 0) * IN_DIM) + kh * 98;
    const float4* xr1 = (const float4*)(x  + (b0 + 1) * IN_DIM) + kh * 98;
    const float4* xr2 = (const float4*)(x  + (b0 + 2) * IN_DIM) + kh * 98;
    const float4* xr3 = (const float4*)(x  + (b0 + 3) * IN_DIM) + kh * 98;
    const float4* wr0 = (const float4*)(W1 + (h0 + 0) * IN_DIM) + kh * 98;
    const float4* wr1 = (const float4*)(W1 + (h0 + 1) * IN_DIM) + kh * 98;
    const float4* wr2 = (const float4*)(W1 + (h0 + 2) * IN_DIM) + kh * 98;
    const float4* wr3 = (const float4*)(W1 + (h0 + 3) * IN_DIM) + kh * 98;

    float v[16];
#pragma unroll
    for (int i = 0; i < 16; i++) v[i] = 0.f;

    const float4 z4 = make_float4(0.f, 0.f, 0.f, 0.f);
#pragma unroll
    for (int t = 0; t < 4; t++) {                 // 98 float4 per half-row
        int idx = lane + 32 * t;
        bool ok = (idx < 98);
        float4 xv[4], wv[4];
        xv[0] = ok ? xr0[idx] : z4;  xv[1] = ok ? xr1[idx] : z4;
        xv[2] = ok ? xr2[idx] : z4;  xv[3] = ok ? xr3[idx] : z4;
        wv[0] = ok ? wr0[idx] : z4;  wv[1] = ok ? wr1[idx] : z4;
        wv[2] = ok ? wr2[idx] : z4;  wv[3] = ok ? wr3[idx] : z4;
#pragma unroll
        for (int i = 0; i < 4; i++)
#pragma unroll
            for (int j = 0; j < 4; j++) {
                float a = v[i * 4 + j];
                a = fmaf(xv[i].x, wv[j].x, a);
                a = fmaf(xv[i].y, wv[j].y, a);
                a = fmaf(xv[i].z, wv[j].z, a);
                a = fmaf(xv[i].w, wv[j].w, a);
                v[i * 4 + j] = a;
            }
    }

    // binary fold: 16 sums -> lane l holds total of index k=(l>>1)&15
#pragma unroll
    for (int i = 0; i < 8; i++) {
        float send = (lane & 16) ? v[i] : v[i + 8];
        float recv = __shfl_xor_sync(0xffffffffu, send, 16);
        v[i] = ((lane & 16) ? v[i + 8] : v[i]) + recv;
    }
#pragma unroll
    for (int i = 0; i < 4; i++) {
        float send = (lane & 8) ? v[i] : v[i + 4];
        float recv = __shfl_xor_sync(0xffffffffu, send, 8);
        v[i] = ((lane & 8) ? v[i + 4] : v[i]) + recv;
    }
#pragma unroll
    for (int i = 0; i < 2; i++) {
        float send = (lane & 4) ? v[i] : v[i + 2];
        float recv = __shfl_xor_sync(0xffffffffu, send, 4);
        v[i] = ((lane & 4) ? v[i + 2] : v[i]) + recv;
    }
    {
        float send = (lane & 2) ? v[0] : v[1];
        float recv = __shfl_xor_sync(0xffffffffu, send, 2);
        v[0] = ((lane & 2) ? v[1] : v[0]) + recv;
    }
    v[0] += __shfl_xor_sync(0xffffffffu, v[0], 1);

    int k = (lane >> 1) & 15;
    if (kh == 1 && (lane & 1) == 0) part[pid][k] = v[0];
    __syncthreads();
    if (kh == 0 && (lane & 1) == 0) {
        int i = k >> 2, j = k & 3;
        float z = v[0] + part[pid][k] + b1[h0 + j];
        g_h[(b0 + i) * HIDDEN + h0 + j] = 1.0f / (1.0f + expf(-z));
    }
}

// ---------------- kernel 2: phase+A, unrank, Glynn (f32x2), W2 epilogue ---
__global__ void __launch_bounds__(256) k_perm(const float* __restrict__ wlre,
                                              const float* __restrict__ wlim,
                                              const float* __restrict__ wrre,
                                              const float* __restrict__ wrim,
                                              const float* __restrict__ W2) {
    int b = blockIdx.y, chunk = blockIdx.x, tid = threadIdx.x;
    __shared__ float2 ph[MODES];
    __shared__ float2 Ash[50];
    __shared__ float  sm_p[256];

    if (tid < MODES) {
        float th = 0.f;
#pragma unroll
        for (int j = 0; j < 10; j++) th += g_h[b * HIDDEN + j * 10 + tid];
        float sn, cn;
        sincosf(th, &sn, &cn);
        ph[tid] = make_float2(cn, sn);
    }
    __syncthreads();

    if (tid < 50) {
        int p = tid / 5, j = tid % 5, c = 2 * j;   // IN_COLS = {0,2,4,6,8}
        float2 acc = make_float2(0.f, 0.f);
#pragma unroll
        for (int q = 0; q < MODES; q++) {
            float2 wr = make_float2(wrre[p * 10 + q], wrim[p * 10 + q]);
            float2 wl = make_float2(wlre[q * 10 + c], wlim[q * 10 + c]);
            float2 t  = cmul(cmul(wr, ph[q]), wl);
            acc.x += t.x; acc.y += t.y;
        }
        Ash[tid] = acc;
    }
    __syncthreads();

    int s  = chunk * 256 + tid;
    int sc = (s < NSTATES) ? s : (NSTATES - 1);

    // unrank combinations_with_replacement(10,5), rank sc
    int r = sc, prev = 0;
    int m[5];
    int fact = 1, run = 1;
#pragma unroll
    for (int i = 0; i < 5; i++) {
        int kk = 4 - i;
        int vv = prev;
        for (;;) {
            int c = g_binom[13 - vv][kk];
            if (r < c) break;
            r -= c;
            vv++;
        }
        m[i] = vv - i;
        prev = vv + 1;
        if (i && m[i] == m[i - 1]) { run++; fact *= run; }
        else run = 1;
    }
    float invf = 1.0f / ((float)fact * 256.0f);   // Glynn 2^{2(1-n)} folded in

    ull row[5][5];
#pragma unroll
    for (int n = 0; n < 5; n++) {
#pragma unroll
        for (int j = 0; j < 5; j++) {
            float2 t = Ash[m[n] * 5 + j];
            row[n][j] = pk2(t.x, t.y);
        }
    }

    // Glynn, Gray-coded, packed f32x2
    ull cs[5];
#pragma unroll
    for (int j = 0; j < 5; j++)
        cs[j] = padd(padd(padd(row[0][j], row[1][j]),
                          padd(row[2][j], row[3][j])), row[4][j]);

    float2 c0 = upk2(cs[0]), c1 = upk2(cs[1]), c2 = upk2(cs[2]),
           c3 = upk2(cs[3]), c4 = upk2(cs[4]);
    float2 pr = cmul(cmul(cmul(c0, c1), cmul(c2, c3)), c4);
    ull acc = pk2(pr.x, pr.y);            // k = 0 term, sign +1

#pragma unroll
    for (int k = 1; k < 16; k++) {
        int rb = (k & 1) ? 1 : (k & 2) ? 2 : (k & 4) ? 3 : 4;   // ctz(k)+1
        unsigned ng = (unsigned)k ^ ((unsigned)k >> 1);
        float sg = ((ng >> (rb - 1)) & 1u) ? -2.f : 2.f;
        ull sgp = pk2(sg, sg);
#pragma unroll
        for (int j = 0; j < 5; j++)
            cs[j] = pfma(sgp, row[rb][j], cs[j]);
        c0 = upk2(cs[0]); c1 = upk2(cs[1]); c2 = upk2(cs[2]);
        c3 = upk2(cs[3]); c4 = upk2(cs[4]);
        pr = cmul(cmul(cmul(c0, c1), cmul(c2, c3)), c4);
        float s2 = (k & 1) ? -1.f : 1.f;
        acc = pfma(pk2(s2, s2), pk2(pr.x, pr.y), acc);
    }

    float2 af = upk2(acc);
    float p = (af.x * af.x + af.y * af.y) * invf;
    if (s >= NSTATES) p = 0.f;
    sm_p[tid] = p;
    __syncthreads();

    // block-level prob @ W2^T : warp w reduces class w (warps 0,1 also 8,9)
    int w = tid >> 5, lane = tid & 31;
#pragma unroll 1
    for (int pass = 0; pass < 2; pass++) {
        int c = w + pass * 8;
        if (pass == 1 && w >= 2) break;
        float v = 0.f;
#pragma unroll
        for (int i = 0; i < 8; i++) {
            int sl = lane * 8 + i;
            int gi = chunk * 256 + sl;
            gi = (gi < NSTATES) ? gi : (NSTATES - 1);
            v = fmaf(sm_p[sl], W2[c * NSTATES + gi], v);
        }
#pragma unroll
        for (int o = 16; o; o >>= 1) v += __shfl_xor_sync(0xffffffffu, v, o);
        if (lane == 0) g_part[(b * SCHUNKS + chunk) * NCLS + c] = v;
    }
}

// ---------------- kernel 3: tiny final reduce ------------------------------
__global__ void k_fin(const float* __restrict__ b2, float* __restrict__ out) {
    int idx = blockIdx.x * 256 + threadIdx.x;
    if (idx >= BATCH * NCLS) return;
    int b = idx / NCLS, c = idx % NCLS;
    float v = b2[c];
#pragma unroll
    for (int k = 0; k < SCHUNKS; k++) v += g_part[(b * SCHUNKS + k) * NCLS + c];
    out[idx] = v;
}

// ---------------- launch ---------------------------------------------------
extern "C" void kernel_launch(void* const* d_in, const int* in_sizes, int n_in,
                              void* d_out, int out_size) {
    const float* x    = (const float*)d_in[0];
    const float* W1   = (const float*)d_in[1];
    const float* b1   = (const float*)d_in[2];
    const float* wlre = (const float*)d_in[3];
    const float* wlim = (const float*)d_in[4];
    const float* wrre = (const float*)d_in[5];
    const float* wrim = (const float*)d_in[6];
    const float* W2   = (const float*)d_in[7];
    const float* b2   = (const float*)d_in[8];
    float* out = (float*)d_out;

    k_mlp<<<200, 256>>>(x, W1, b1);
    dim3 gp(SCHUNKS, BATCH);
    k_perm<<<gp, 256>>>(wlre, wlim, wrre, wrim, W2);
    k_fin<<<(BATCH * NCLS + 255) / 256, 256>>>(b2, out);
}

// round 7
// speedup vs baseline: 1.1215x; 1.1215x over previous
#include <cuda_runtime.h>
#include <math.h>

#define BATCH   128
#define IN_DIM  784
#define HIDDEN  100
#define MODES   10
#define NSTATES 2002
#define NCLS    10
#define SCHUNKS 8

// ---------------- scratch (__device__ globals; no allocation allowed) ------
__device__ float    g_h[BATCH * HIDDEN];             // sigmoid activations
__device__ float    g_part[BATCH * SCHUNKS * NCLS];  // partial W2 sums
__device__ unsigned g_states[NSTATES];               // 5 nibbles: row indices
__device__ float    g_invfact[NSTATES];              // 1/(fact*256)
__device__ int      g_cnt[BATCH];                    // finisher counters (zero-init)

// binomial C(n,k), n=0..13, k=0..4
__device__ const short g_binom[14][5] = {
    {1, 0, 0, 0, 0},  {1, 1, 0, 0, 0},   {1, 2, 1, 0, 0},    {1, 3, 3, 1, 0},
    {1, 4, 6, 4, 1},  {1, 5,10,10, 5},   {1, 6,15,20,15},    {1, 7,21,35,35},
    {1, 8,28,56,70},  {1, 9,36,84,126},  {1,10,45,120,210},  {1,11,55,165,330},
    {1,12,66,220,495},{1,13,78,286,715}
};

__device__ __forceinline__ float2 cmul(float2 a, float2 b) {
    return make_float2(fmaf(a.x, b.x, -(a.y * b.y)),
                       fmaf(a.x, b.y,  a.y * b.x));
}

// ---------------- kernel 1: MLP (2b x 4h tiles, K-split x2) + unrank ------
// Blocks 0..399: MLP, 4 tile-pairs per block (3200 warps total).
// Blocks 400..407: unrank combinations_with_replacement(10,5).
__global__ void __launch_bounds__(256) k_mlp(const float* __restrict__ x,
                                             const float* __restrict__ W1,
                                             const float* __restrict__ b1) {
    int wid  = threadIdx.x >> 5;
    int lane = threadIdx.x & 31;

    if (blockIdx.x >= 400) {
        int s = (blockIdx.x - 400) * 256 + threadIdx.x;
        if (s >= NSTATES) return;
        int r = s, prev = 0;
        int m[5];
        int fact = 1, run = 1;
#pragma unroll
        for (int i = 0; i < 5; i++) {
            int kk = 4 - i;
            int vv = prev;
            for (;;) {
                int c = g_binom[13 - vv][kk];
                if (r < c) break;
                r -= c;
                vv++;
            }
            m[i] = vv - i;
            prev = vv + 1;
            if (i && m[i] == m[i - 1]) { run++; fact *= run; }
            else run = 1;
        }
        unsigned u = 0;
#pragma unroll
        for (int i = 0; i < 5; i++) u |= ((unsigned)m[i]) << (4 * i);
        g_states[s]  = u;
        g_invfact[s] = 1.0f / ((float)fact * 256.0f);   // Glynn 2^{2(1-n)} folded
        return;
    }

    int pid = wid >> 1;                  // tile-pair in block (0..3)
    int kh  = wid & 1;                   // K half
    int g   = blockIdx.x * 4 + pid;      // 1600 tile pairs
    int b0  = (g & 63) * 2;              // 64 batch tiles of 2
    int h0  = (g >> 6) * 4;              // 25 hidden tiles of 4

    __shared__ float part[4][8];

    const float4* xr0 = (const float4*)(x  + (b0 + 0) * IN_DIM) + kh * 98;
    const float4* xr1 = (const float4*)(x  + (b0 + 1) * IN_DIM) + kh * 98;
    const float4* wr0 = (const float4*)(W1 + (h0 + 0) * IN_DIM) + kh * 98;
    const float4* wr1 = (const float4*)(W1 + (h0 + 1) * IN_DIM) + kh * 98;
    const float4* wr2 = (const float4*)(W1 + (h0 + 2) * IN_DIM) + kh * 98;
    const float4* wr3 = (const float4*)(W1 + (h0 + 3) * IN_DIM) + kh * 98;

    float v[8];
#pragma unroll
    for (int i = 0; i < 8; i++) v[i] = 0.f;

    const float4 z4 = make_float4(0.f, 0.f, 0.f, 0.f);
#pragma unroll
    for (int t = 0; t < 4; t++) {                 // 98 float4 per half-row
        int idx = lane + 32 * t;
        bool ok = (idx < 98);
        float4 x0 = ok ? xr0[idx] : z4;
        float4 x1 = ok ? xr1[idx] : z4;
        float4 w0 = ok ? wr0[idx] : z4;
        float4 w1 = ok ? wr1[idx] : z4;
        float4 w2 = ok ? wr2[idx] : z4;
        float4 w3 = ok ? wr3[idx] : z4;
#pragma unroll
        for (int j = 0; j < 4; j++) {
            float4 wv = (j == 0) ? w0 : (j == 1) ? w1 : (j == 2) ? w2 : w3;
            float a0 = v[j], a1 = v[4 + j];
            a0 = fmaf(x0.x, wv.x, a0); a0 = fmaf(x0.y, wv.y, a0);
            a0 = fmaf(x0.z, wv.z, a0); a0 = fmaf(x0.w, wv.w, a0);
            a1 = fmaf(x1.x, wv.x, a1); a1 = fmaf(x1.y, wv.y, a1);
            a1 = fmaf(x1.z, wv.z, a1); a1 = fmaf(x1.w, wv.w, a1);
            v[j] = a0; v[4 + j] = a1;
        }
    }
    // v[i*4+j] layout: i = batch (0..1) -> indices {0..3}=b0, {4..7}=b0+1
    // binary fold: 8 -> 1 value per lane; owner k = bit16*4 + bit8*2 + bit4
#pragma unroll
    for (int i = 0; i < 4; i++) {
        float send = (lane & 16) ? v[i] : v[i + 4];
        float recv = __shfl_xor_sync(0xffffffffu, send, 16);
        v[i] = ((lane & 16) ? v[i + 4] : v[i]) + recv;
    }
#pragma unroll
    for (int i = 0; i < 2; i++) {
        float send = (lane & 8) ? v[i] : v[i + 2];
        float recv = __shfl_xor_sync(0xffffffffu, send, 8);
        v[i] = ((lane & 8) ? v[i + 2] : v[i]) + recv;
    }
    {
        float send = (lane & 4) ? v[0] : v[1];
        float recv = __shfl_xor_sync(0xffffffffu, send, 4);
        v[0] = ((lane & 4) ? v[1] : v[0]) + recv;
    }
    v[0] += __shfl_xor_sync(0xffffffffu, v[0], 2);
    v[0] += __shfl_xor_sync(0xffffffffu, v[0], 1);

    // k = 4*bit(lane,16) + 2*bit(lane,8) + bit(lane,4); fold kept upper at set bits
    int k = (((lane >> 4) & 1) << 2) | (((lane >> 3) & 1) << 1) | ((lane >> 2) & 1);
    // v index was i*?? -> mapping: fold16 upper half = indices 4..7 (batch 1)
    // so bit16 => batch bit, bit8 => j bit1, bit4 => j bit0
    int bi = (k >> 2) & 1, j = k & 3;

    if (kh == 1 && (lane & 3) == 0) part[pid][k] = v[0];
    __syncthreads();
    if (kh == 0 && (lane & 3) == 0) {
        float z = v[0] + part[pid][k] + b1[h0 + j];
        g_h[(b0 + bi) * HIDDEN + h0 + j] = 1.0f / (1.0f + expf(-z));
    }
}

// ---------------- kernel 2: phase+A, Glynn perm (scalar), W2 + finisher ---
__global__ void __launch_bounds__(256) k_perm(const float* __restrict__ wlre,
                                              const float* __restrict__ wlim,
                                              const float* __restrict__ wrre,
                                              const float* __restrict__ wrim,
                                              const float* __restrict__ W2,
                                              const float* __restrict__ b2,
                                              float* __restrict__ out) {
    int b = blockIdx.y, chunk = blockIdx.x, tid = threadIdx.x;
    __shared__ float2 ph[MODES];
    __shared__ float2 Ash[50];
    __shared__ float  sm_p[256];
    __shared__ int    amLast;

    if (tid < MODES) {
        float th = 0.f;
#pragma unroll
        for (int j = 0; j < 10; j++) th += g_h[b * HIDDEN + j * 10 + tid];
        float sn, cn;
        sincosf(th, &sn, &cn);
        ph[tid] = make_float2(cn, sn);
    }
    __syncthreads();

    if (tid < 50) {
        int p = tid / 5, j = tid % 5, c = 2 * j;   // IN_COLS = {0,2,4,6,8}
        float2 acc = make_float2(0.f, 0.f);
#pragma unroll
        for (int q = 0; q < MODES; q++) {
            float2 wr = make_float2(wrre[p * 10 + q], wrim[p * 10 + q]);
            float2 wl = make_float2(wlre[q * 10 + c], wlim[q * 10 + c]);
            float2 t  = cmul(cmul(wr, ph[q]), wl);
            acc.x += t.x; acc.y += t.y;
        }
        Ash[tid] = acc;
    }
    __syncthreads();

    int s  = chunk * 256 + tid;
    int sc = (s < NSTATES) ? s : (NSTATES - 1);
    unsigned u = g_states[sc];
    float invf = g_invfact[sc];

    float2 row[5][5];
#pragma unroll
    for (int n = 0; n < 5; n++) {
        int r = (u >> (4 * n)) & 15;
#pragma unroll
        for (int j = 0; j < 5; j++) row[n][j] = Ash[r * 5 + j];
    }

    // Glynn, Gray-coded, pure scalar (fastest variant measured)
    float2 cs[5];
#pragma unroll
    for (int j = 0; j < 5; j++) {
        cs[j].x = ((row[0][j].x + row[1][j].x) + (row[2][j].x + row[3][j].x)) + row[4][j].x;
        cs[j].y = ((row[0][j].y + row[1][j].y) + (row[2][j].y + row[3][j].y)) + row[4][j].y;
    }
    float2 pr = cmul(cmul(cmul(cs[0], cs[1]), cmul(cs[2], cs[3])), cs[4]);
    float2 acc = pr;                       // k = 0 term, sign +1

#pragma unroll
    for (int k = 1; k < 16; k++) {
        int rb = (k & 1) ? 1 : (k & 2) ? 2 : (k & 4) ? 3 : 4;   // ctz(k)+1
        unsigned ng = (unsigned)k ^ ((unsigned)k >> 1);
        float sg = ((ng >> (rb - 1)) & 1u) ? -2.f : 2.f;
#pragma unroll
        for (int j = 0; j < 5; j++) {
            cs[j].x = fmaf(sg, row[rb][j].x, cs[j].x);
            cs[j].y = fmaf(sg, row[rb][j].y, cs[j].y);
        }
        pr = cmul(cmul(cmul(cs[0], cs[1]), cmul(cs[2], cs[3])), cs[4]);
        float s2 = (k & 1) ? -1.f : 1.f;                        // parity(gray(k))
        acc.x = fmaf(s2, pr.x, acc.x);
        acc.y = fmaf(s2, pr.y, acc.y);
    }

    float p = (acc.x * acc.x + acc.y * acc.y) * invf;
    if (s >= NSTATES) p = 0.f;
    sm_p[tid] = p;
    __syncthreads();

    // block-level prob @ W2^T : warp w -> class w (warps 0,1 also 8,9)
    int w = tid >> 5, lane = tid & 31;
#pragma unroll 1
    for (int pass = 0; pass < 2; pass++) {
        int c = w + pass * 8;
        if (pass == 1 && w >= 2) break;
        float v = 0.f;
#pragma unroll
        for (int i = 0; i < 8; i++) {
            int sl = i * 32 + lane;                 // stride-1: no LDS conflicts
            int gi = chunk * 256 + sl;
            gi = (gi < NSTATES) ? gi : (NSTATES - 1);
            v = fmaf(sm_p[sl], W2[c * NSTATES + gi], v);
        }
#pragma unroll
        for (int o = 16; o; o >>= 1) v += __shfl_xor_sync(0xffffffffu, v, o);
        if (lane == 0) g_part[(b * SCHUNKS + chunk) * NCLS + c] = v;
    }
    __syncthreads();

    // deterministic last-block finisher for this batch
    if (tid == 0) {
        __threadfence();
        int old = atomicAdd(&g_cnt[b], 1);
        amLast = (old == SCHUNKS - 1) ? 1 : 0;
    }
    __syncthreads();
    if (amLast) {
        __threadfence();
        if (tid < NCLS) {
            float v = b2[tid];
#pragma unroll
            for (int k = 0; k < SCHUNKS; k++)
                v += g_part[(b * SCHUNKS + k) * NCLS + tid];
            out[b * NCLS + tid] = v;
        }
        if (tid == 0) g_cnt[b] = 0;    // reset for next graph replay
    }
}

// ---------------- launch ---------------------------------------------------
extern "C" void kernel_launch(void* const* d_in, const int* in_sizes, int n_in,
                              void* d_out, int out_size) {
    const float* x    = (const float*)d_in[0];
    const float* W1   = (const float*)d_in[1];
    const float* b1   = (const float*)d_in[2];
    const float* wlre = (const float*)d_in[3];
    const float* wlim = (const float*)d_in[4];
    const float* wrre = (const float*)d_in[5];
    const float* wrim = (const float*)d_in[6];
    const float* W2   = (const float*)d_in[7];
    const float* b2   = (const float*)d_in[8];
    float* out = (float*)d_out;

    k_mlp<<<408, 256>>>(x, W1, b1);
    dim3 gp(SCHUNKS, BATCH);
    k_perm<<<gp, 256>>>(wlre, wlim, wrre, wrim, W2, b2, out);
}